// round 5
// baseline (speedup 1.0000x reference)
#include <cuda_runtime.h>
#include <cstdint>

// Problem constants
#define BB   2048
#define HH   2048
#define RNK  64
#define LL   32

#define NKG  16          // split-K groups for GEMM1 (k per block = 128)
#define KCH  (HH / NKG)  // 128
#define MT   64          // M tile (samples)
#define HT   128         // h tile for GEMM2
#define TPB  256         // 8 warps
#define ST   68          // padded smem stride: bank=(4*gid+tig)%32 -> conflict-free

// Scratch (device globals — no allocations allowed)
__device__ int    g_offsets[LL + 1];
__device__ int    g_sorted[BB];
__device__ float  g_partial[(size_t)NKG * BB * RNK];   // 8 MB, indexed by sorted pos
__device__ float  g_proj[(size_t)BB * RNK];            // indexed by sorted pos

#define MMA_TF32(c0,c1,c2,c3,a0,a1,a2,a3,b0,b1)                         \
    asm("mma.sync.aligned.m16n8k8.row.col.f32.tf32.tf32.f32 "           \
        "{%0,%1,%2,%3}, {%4,%5,%6,%7}, {%8,%9}, {%0,%1,%2,%3};"         \
        : "+f"(c0), "+f"(c1), "+f"(c2), "+f"(c3)                        \
        : "r"(a0), "r"(a1), "r"(a2), "r"(a3), "r"(b0), "r"(b1))

__device__ __forceinline__ void cpa16(uint32_t dst, const void* src, uint32_t sz) {
    asm volatile("cp.async.cg.shared.global [%0], [%1], 16, %2;"
                 :: "r"(dst), "l"(src), "r"(sz));
}
__device__ __forceinline__ void cpa_commit_wait() {
    asm volatile("cp.async.commit_group;");
    asm volatile("cp.async.wait_group 0;");
}

// ---------------------------------------------------------------------------
// Kernel 1: stable counting sort of samples by layer id (deterministic).
// ---------------------------------------------------------------------------
__global__ void setup_kernel(const int* __restrict__ ids) {
    __shared__ int A[LL * 256];
    __shared__ int S[256];
    int t = threadIdx.x;

    #pragma unroll
    for (int l = 0; l < LL; l++) A[l * 256 + t] = 0;
    int seg = t * (BB / 256);
    #pragma unroll
    for (int i = 0; i < BB / 256; i++) {
        int lid = ids[seg + i];
        A[lid * 256 + t]++;
    }
    __syncthreads();

    int base = t * 32;
    int sum = 0;
    #pragma unroll
    for (int j = 0; j < 32; j++) { int x = A[base + j]; A[base + j] = sum; sum += x; }
    S[t] = sum;
    int mysum = sum;
    __syncthreads();
    for (int d = 1; d < 256; d <<= 1) {
        int add = (t >= d) ? S[t - d] : 0;
        __syncthreads();
        S[t] += add;
        __syncthreads();
    }
    int excl = S[t] - mysum;
    #pragma unroll
    for (int j = 0; j < 32; j++) A[base + j] += excl;
    __syncthreads();

    if (t < LL) g_offsets[t] = A[t * 256];
    if (t == 0) g_offsets[LL] = BB;

    #pragma unroll
    for (int i = 0; i < BB / 256; i++) {
        int s = seg + i;
        int lid = ids[s];
        int p = A[lid * 256 + t];
        A[lid * 256 + t] = p + 1;
        g_sorted[p] = s;
    }
}

// ---------------------------------------------------------------------------
// Kernel 2: GEMM1 split-K, tf32 mma, cp.async raw-fp32 staging.
// block = (kg, layer); 8 warps; warp = m32 (wm) x n16 (wn).
// partial[kg][p][r] = sum_{k in chunk} v[l][k][r] * z[sorted[p]][k]
// ---------------------------------------------------------------------------
__global__ __launch_bounds__(TPB, 4) void proj_kernel(const float* __restrict__ z,
                                                      const float* __restrict__ v) {
    extern __shared__ __align__(16) uint32_t smem1[];
    uint32_t* sz = smem1;              // [MT][ST]   z tile (raw fp32 bits)
    uint32_t* sv = smem1 + MT * ST;    // [64][ST]   v tile

    int t = threadIdx.x, lane = t & 31, w = t >> 5;
    int gid = lane >> 2, tig = lane & 3;
    int wm = w & 1, wn = w >> 1;       // m32 half, n16 quarter
    int kg = blockIdx.x, l = blockIdx.y;

    uint32_t sz_b = (uint32_t)__cvta_generic_to_shared(sz);
    uint32_t sv_b = (uint32_t)__cvta_generic_to_shared(sv);

    int off = g_offsets[l];
    int cnt = g_offsets[l + 1] - off;

    for (int m0 = 0; m0 < cnt; m0 += MT) {
        int nc = min(MT, cnt - m0);

        float acc[2][2][4];
        #pragma unroll
        for (int mt = 0; mt < 2; mt++)
            #pragma unroll
            for (int j = 0; j < 2; j++)
                #pragma unroll
                for (int q = 0; q < 4; q++) acc[mt][j][q] = 0.0f;

        #pragma unroll
        for (int kk = 0; kk < KCH / 64; kk++) {
            int k0 = kg * KCH + kk * 64;
            __syncthreads();
            // stage z tile (rows = samples, zero-fill pad) raw fp32
            #pragma unroll
            for (int i = 0; i < (MT * 16) / TPB; i++) {     // 4 iters
                int idx = t + i * TPB;
                int row = idx >> 4, c4 = idx & 15;
                const float* src = z;
                uint32_t szb = 0;
                if (row < nc) {
                    int gs = g_sorted[off + m0 + row];
                    src = z + (size_t)gs * HH + k0 + c4 * 4;
                    szb = 16;
                }
                cpa16(sz_b + (row * ST + c4 * 4) * 4, src, szb);
            }
            // stage v tile (64 k rows x 64 r)
            #pragma unroll
            for (int i = 0; i < (64 * 16) / TPB; i++) {     // 4 iters
                int idx = t + i * TPB;
                int row = idx >> 4, c4 = idx & 15;
                cpa16(sv_b + (row * ST + c4 * 4) * 4,
                      v + ((size_t)l * HH + k0 + row) * RNK + c4 * 4, 16);
            }
            cpa_commit_wait();
            __syncthreads();

            #pragma unroll
            for (int ks = 0; ks < 8; ks++) {
                int kb = ks * 8 + tig;
                uint32_t b0[2], b1[2];
                #pragma unroll
                for (int j = 0; j < 2; j++) {
                    int n = wn * 16 + j * 8 + gid;
                    b0[j] = sv[kb * ST + n];
                    b1[j] = sv[(kb + 4) * ST + n];
                }
                #pragma unroll
                for (int mt = 0; mt < 2; mt++) {
                    const uint32_t* szr = sz + (wm * 32 + mt * 16 + gid) * ST;
                    uint32_t a0 = szr[kb];
                    uint32_t a1 = szr[8 * ST + kb];
                    uint32_t a2 = szr[kb + 4];
                    uint32_t a3 = szr[8 * ST + kb + 4];
                    #pragma unroll
                    for (int j = 0; j < 2; j++)
                        MMA_TF32(acc[mt][j][0], acc[mt][j][1], acc[mt][j][2], acc[mt][j][3],
                                 a0, a1, a2, a3, b0[j], b1[j]);
                }
            }
        }

        float* pb = g_partial + (size_t)kg * BB * RNK;
        #pragma unroll
        for (int mt = 0; mt < 2; mt++) {
            int rbase = wm * 32 + mt * 16 + gid;
            #pragma unroll
            for (int j = 0; j < 2; j++) {
                int col = wn * 16 + j * 8 + 2 * tig;
                if (rbase < nc)
                    *(float2*)&pb[(size_t)(off + m0 + rbase) * RNK + col] =
                        make_float2(acc[mt][j][0], acc[mt][j][1]);
                if (rbase + 8 < nc)
                    *(float2*)&pb[(size_t)(off + m0 + rbase + 8) * RNK + col] =
                        make_float2(acc[mt][j][2], acc[mt][j][3]);
            }
        }
    }
}

// ---------------------------------------------------------------------------
// Kernel 3: deterministic split-K reduction (16 groups).
// ---------------------------------------------------------------------------
__global__ void reduce_kernel() {
    int i = blockIdx.x * blockDim.x + threadIdx.x;
    const int n4 = BB * RNK / 4;
    if (i >= n4) return;
    const float4* p = (const float4*)g_partial;
    float4 s = p[i];
    #pragma unroll
    for (int kc = 1; kc < NKG; kc++) {
        float4 q = p[(size_t)kc * n4 + i];
        s.x += q.x; s.y += q.y; s.z += q.z; s.w += q.w;
    }
    ((float4*)g_proj)[i] = s;
}

// ---------------------------------------------------------------------------
// Kernel 4: GEMM2 + epilogue, tf32 mma, cp.async staging.
// block = (h-tile 128, layer); 8 warps; warp = m32 (wm) x n32 (wn).
// out[gs][h] = z[gs][h] + sum_r u[l][h][r] * proj[p][r]
// ---------------------------------------------------------------------------
__global__ __launch_bounds__(TPB, 4) void out_kernel(const float* __restrict__ z,
                                                     const float* __restrict__ u,
                                                     float* __restrict__ out) {
    extern __shared__ __align__(16) uint32_t smem2[];
    uint32_t* sp = smem2;              // [MT][ST]  proj tile
    uint32_t* su = smem2 + MT * ST;    // [HT][ST]  u tile

    int t = threadIdx.x, lane = t & 31, w = t >> 5;
    int gid = lane >> 2, tig = lane & 3;
    int wm = w & 1, wn = w >> 1;       // m32 half, n32 quarter
    int hb = blockIdx.x, l = blockIdx.y;
    int h0 = hb * HT;

    uint32_t sp_b = (uint32_t)__cvta_generic_to_shared(sp);
    uint32_t su_b = (uint32_t)__cvta_generic_to_shared(su);

    int off = g_offsets[l];
    int cnt = g_offsets[l + 1] - off;
    if (cnt == 0) return;

    // stage u tile once: su[h][r], raw fp32
    #pragma unroll
    for (int i = 0; i < (HT * 16) / TPB; i++) {             // 8 iters
        int idx = t + i * TPB;
        int row = idx >> 4, c4 = idx & 15;
        cpa16(su_b + (row * ST + c4 * 4) * 4,
              u + ((size_t)l * HH + h0 + row) * RNK + c4 * 4, 16);
    }

    for (int m0 = 0; m0 < cnt; m0 += MT) {
        int nc = min(MT, cnt - m0);
        __syncthreads();   // previous sp consumed
        #pragma unroll
        for (int i = 0; i < (MT * 16) / TPB; i++) {         // 4 iters
            int idx = t + i * TPB;
            int row = idx >> 4, c4 = idx & 15;
            const float* src = g_proj;
            uint32_t szb = 0;
            if (row < nc) {
                src = g_proj + (size_t)(off + m0 + row) * RNK + c4 * 4;
                szb = 16;
            }
            cpa16(sp_b + (row * ST + c4 * 4) * 4, src, szb);
        }
        cpa_commit_wait();
        __syncthreads();

        float acc[2][4][4];
        #pragma unroll
        for (int mt = 0; mt < 2; mt++)
            #pragma unroll
            for (int j = 0; j < 4; j++)
                #pragma unroll
                for (int q = 0; q < 4; q++) acc[mt][j][q] = 0.0f;

        #pragma unroll
        for (int ks = 0; ks < 8; ks++) {
            int kb = ks * 8 + tig;
            uint32_t b0[4], b1[4];
            #pragma unroll
            for (int j = 0; j < 4; j++) {
                int n = wn * 32 + j * 8 + gid;
                b0[j] = su[n * ST + kb];
                b1[j] = su[n * ST + kb + 4];
            }
            #pragma unroll
            for (int mt = 0; mt < 2; mt++) {
                const uint32_t* spr = sp + (wm * 32 + mt * 16 + gid) * ST;
                uint32_t a0 = spr[kb];
                uint32_t a1 = spr[8 * ST + kb];
                uint32_t a2 = spr[kb + 4];
                uint32_t a3 = spr[8 * ST + kb + 4];
                #pragma unroll
                for (int j = 0; j < 4; j++)
                    MMA_TF32(acc[mt][j][0], acc[mt][j][1], acc[mt][j][2], acc[mt][j][3],
                             a0, a1, a2, a3, b0[j], b1[j]);
            }
        }

        // epilogue: out = z + delta
        #pragma unroll
        for (int mt = 0; mt < 2; mt++) {
            #pragma unroll
            for (int half = 0; half < 2; half++) {
                int rr = wm * 32 + mt * 16 + gid + half * 8;
                if (rr < nc) {
                    int gs = g_sorted[off + m0 + rr];
                    const float* zrow = z + (size_t)gs * HH + h0;
                    float* orow = out + (size_t)gs * HH + h0;
                    #pragma unroll
                    for (int j = 0; j < 4; j++) {
                        int col = wn * 32 + j * 8 + 2 * tig;
                        float2 zz = *(const float2*)&zrow[col];
                        *(float2*)&orow[col] = make_float2(zz.x + acc[mt][j][half * 2 + 0],
                                                           zz.y + acc[mt][j][half * 2 + 1]);
                    }
                }
            }
        }
    }
}

// ---------------------------------------------------------------------------
extern "C" void kernel_launch(void* const* d_in, const int* in_sizes, int n_in,
                              void* d_out, int out_size) {
    const float* z   = (const float*)d_in[0];
    const int*   ids = (const int*)  d_in[1];
    const float* u   = (const float*)d_in[2];
    const float* v   = (const float*)d_in[3];
    float*       out = (float*)d_out;

    const int proj_smem = (MT + 64) * ST * 4;      // 34.8 KB
    const int out_smem  = (MT + HT) * ST * 4;      // 52.2 KB
    cudaFuncSetAttribute(proj_kernel, cudaFuncAttributeMaxDynamicSharedMemorySize, proj_smem);
    cudaFuncSetAttribute(out_kernel,  cudaFuncAttributeMaxDynamicSharedMemorySize, out_smem);

    setup_kernel<<<1, 256>>>(ids);
    proj_kernel<<<dim3(NKG, LL), TPB, proj_smem>>>(z, v);
    reduce_kernel<<<(BB * RNK / 4 + 255) / 256, 256>>>();
    out_kernel<<<dim3(HH / HT, LL), TPB, out_smem>>>(z, u, out);
}

// round 7
// speedup vs baseline: 1.2318x; 1.2318x over previous
#include <cuda_runtime.h>
#include <cstdint>

// Problem constants
#define BB   2048
#define HH   2048
#define RNK  64
#define LL   32

#define NKG  8           // split-K groups for GEMM1 (k per block = 256)
#define KCH  (HH / NKG)  // 256
#define KST  128         // K staged per cp.async phase
#define MT   64          // M tile (samples)
#define HT   128         // h tile for GEMM2
#define TPB  256         // 8 warps
#define STA  132         // stride for sample-major tiles, 132 mod 32 == 4
#define STB  72          // stride for k-major v tile,     72 mod 32 == 8
#define STU  68          // stride for n-major u/proj,      68 mod 32 == 4

// Scratch (device globals — no allocations allowed)
__device__ int    g_offsets[LL + 1];
__device__ int    g_sorted[BB];
__device__ float  g_partial[(size_t)NKG * BB * RNK];   // 4 MB, indexed by sorted pos
__device__ float  g_proj[(size_t)BB * RNK];            // indexed by sorted pos

#define MMA_TF32(c0,c1,c2,c3,a0,a1,a2,a3,b0,b1)                         \
    asm("mma.sync.aligned.m16n8k8.row.col.f32.tf32.tf32.f32 "           \
        "{%0,%1,%2,%3}, {%4,%5,%6,%7}, {%8,%9}, {%0,%1,%2,%3};"         \
        : "+f"(c0), "+f"(c1), "+f"(c2), "+f"(c3)                        \
        : "r"(a0), "r"(a1), "r"(a2), "r"(a3), "r"(b0), "r"(b1))

__device__ __forceinline__ void cpa16(uint32_t dst, const void* src, uint32_t sz) {
    asm volatile("cp.async.cg.shared.global [%0], [%1], 16, %2;"
                 :: "r"(dst), "l"(src), "r"(sz));
}
__device__ __forceinline__ void cpa_commit_wait() {
    asm volatile("cp.async.commit_group;");
    asm volatile("cp.async.wait_group 0;");
}

// ---------------------------------------------------------------------------
// Kernel 1: stable counting sort of samples by layer id (deterministic).
// ---------------------------------------------------------------------------
__global__ void setup_kernel(const int* __restrict__ ids) {
    __shared__ int A[LL * 256];
    __shared__ int S[256];
    int t = threadIdx.x;

    #pragma unroll
    for (int l = 0; l < LL; l++) A[l * 256 + t] = 0;
    int seg = t * (BB / 256);
    #pragma unroll
    for (int i = 0; i < BB / 256; i++) {
        int lid = ids[seg + i];
        A[lid * 256 + t]++;
    }
    __syncthreads();

    int base = t * 32;
    int sum = 0;
    #pragma unroll
    for (int j = 0; j < 32; j++) { int x = A[base + j]; A[base + j] = sum; sum += x; }
    S[t] = sum;
    int mysum = sum;
    __syncthreads();
    for (int d = 1; d < 256; d <<= 1) {
        int add = (t >= d) ? S[t - d] : 0;
        __syncthreads();
        S[t] += add;
        __syncthreads();
    }
    int excl = S[t] - mysum;
    #pragma unroll
    for (int j = 0; j < 32; j++) A[base + j] += excl;
    __syncthreads();

    if (t < LL) g_offsets[t] = A[t * 256];
    if (t == 0) g_offsets[LL] = BB;

    #pragma unroll
    for (int i = 0; i < BB / 256; i++) {
        int s = seg + i;
        int lid = ids[s];
        int p = A[lid * 256 + t];
        A[lid * 256 + t] = p + 1;
        g_sorted[p] = s;
    }
}

// ---------------------------------------------------------------------------
// Kernel 2: GEMM1 split-K, tf32 mma, K=128 staged per single cp.async group.
// block = (kg in [0,8), layer); 8 warps; warp = m32 (wm) x n16 (wn).
// partial[kg][p][r] = sum_{k in chunk} v[l][k][r] * z[sorted[p]][k]
// ---------------------------------------------------------------------------
__global__ __launch_bounds__(TPB, 3) void proj_kernel(const float* __restrict__ z,
                                                      const float* __restrict__ v) {
    extern __shared__ __align__(16) uint32_t smem1[];
    uint32_t* sz = smem1;               // [MT][STA]   z tile (raw fp32)  33.8 KB
    uint32_t* sv = smem1 + MT * STA;    // [KST][STB]  v tile            36.9 KB

    int t = threadIdx.x, lane = t & 31, w = t >> 5;
    int gid = lane >> 2, tig = lane & 3;
    int wm = w & 1, wn = w >> 1;
    int kg = blockIdx.x, l = blockIdx.y;

    uint32_t sz_b = (uint32_t)__cvta_generic_to_shared(sz);
    uint32_t sv_b = (uint32_t)__cvta_generic_to_shared(sv);

    int off = g_offsets[l];
    int cnt = g_offsets[l + 1] - off;

    for (int m0 = 0; m0 < cnt; m0 += MT) {
        int nc = min(MT, cnt - m0);

        float acc[2][2][4];
        #pragma unroll
        for (int mt = 0; mt < 2; mt++)
            #pragma unroll
            for (int j = 0; j < 2; j++)
                #pragma unroll
                for (int q = 0; q < 4; q++) acc[mt][j][q] = 0.0f;

        #pragma unroll
        for (int kk = 0; kk < KCH / KST; kk++) {
            int k0 = kg * KCH + kk * KST;
            __syncthreads();
            // stage z tile: 64 samples x 128 k (raw fp32, zero-fill pads)
            #pragma unroll
            for (int i = 0; i < (MT * 32) / TPB; i++) {     // 8 iters
                int idx = t + i * TPB;
                int row = idx >> 5, c4 = idx & 31;
                const float* src = z;
                uint32_t szb = 0;
                if (row < nc) {
                    int gs = g_sorted[off + m0 + row];
                    src = z + (size_t)gs * HH + k0 + c4 * 4;
                    szb = 16;
                }
                cpa16(sz_b + (row * STA + c4 * 4) * 4, src, szb);
            }
            // stage v tile: 128 k rows x 64 r
            #pragma unroll
            for (int i = 0; i < (KST * 16) / TPB; i++) {    // 8 iters
                int idx = t + i * TPB;
                int row = idx >> 4, c4 = idx & 15;
                cpa16(sv_b + (row * STB + c4 * 4) * 4,
                      v + ((size_t)l * HH + k0 + row) * RNK + c4 * 4, 16);
            }
            cpa_commit_wait();
            __syncthreads();

            #pragma unroll
            for (int ks = 0; ks < KST / 8; ks++) {          // 16 iters
                int kb = ks * 8 + tig;
                uint32_t b0[2], b1[2];
                #pragma unroll
                for (int j = 0; j < 2; j++) {
                    int n = wn * 16 + j * 8 + gid;
                    b0[j] = sv[kb * STB + n];
                    b1[j] = sv[(kb + 4) * STB + n];
                }
                #pragma unroll
                for (int mt = 0; mt < 2; mt++) {
                    const uint32_t* szr = sz + (wm * 32 + mt * 16 + gid) * STA;
                    uint32_t a0 = szr[kb];
                    uint32_t a1 = szr[8 * STA + kb];
                    uint32_t a2 = szr[kb + 4];
                    uint32_t a3 = szr[8 * STA + kb + 4];
                    #pragma unroll
                    for (int j = 0; j < 2; j++)
                        MMA_TF32(acc[mt][j][0], acc[mt][j][1], acc[mt][j][2], acc[mt][j][3],
                                 a0, a1, a2, a3, b0[j], b1[j]);
                }
            }
        }

        float* pb = g_partial + (size_t)kg * BB * RNK;
        #pragma unroll
        for (int mt = 0; mt < 2; mt++) {
            int rbase = wm * 32 + mt * 16 + gid;
            #pragma unroll
            for (int j = 0; j < 2; j++) {
                int col = wn * 16 + j * 8 + 2 * tig;
                if (rbase < nc)
                    *(float2*)&pb[(size_t)(off + m0 + rbase) * RNK + col] =
                        make_float2(acc[mt][j][0], acc[mt][j][1]);
                if (rbase + 8 < nc)
                    *(float2*)&pb[(size_t)(off + m0 + rbase + 8) * RNK + col] =
                        make_float2(acc[mt][j][2], acc[mt][j][3]);
            }
        }
    }
}

// ---------------------------------------------------------------------------
// Kernel 3: deterministic split-K reduction (8 groups).
// ---------------------------------------------------------------------------
__global__ void reduce_kernel() {
    int i = blockIdx.x * blockDim.x + threadIdx.x;
    const int n4 = BB * RNK / 4;
    if (i >= n4) return;
    const float4* p = (const float4*)g_partial;
    float4 s = p[i];
    #pragma unroll
    for (int kc = 1; kc < NKG; kc++) {
        float4 q = p[(size_t)kc * n4 + i];
        s.x += q.x; s.y += q.y; s.z += q.z; s.w += q.w;
    }
    ((float4*)g_proj)[i] = s;
}

// ---------------------------------------------------------------------------
// Kernel 4: GEMM2 + fused epilogue. ALL inputs (u, proj, z-epilogue tile)
// staged via ONE cp.async group -> single exposed wait, then MMA + smem epilogue.
// block = (h-tile 128, layer); 8 warps; warp = m32 (wm) x n32 (wn).
// ---------------------------------------------------------------------------
__global__ __launch_bounds__(TPB, 2) void out_kernel(const float* __restrict__ z,
                                                     const float* __restrict__ u,
                                                     float* __restrict__ out) {
    extern __shared__ __align__(16) uint32_t smem2[];
    uint32_t* su  = smem2;                         // [HT][STU]  u tile    34.8 KB
    uint32_t* sp  = smem2 + HT * STU;              // [MT][STU]  proj tile 17.4 KB
    uint32_t* sze = smem2 + HT * STU + MT * STU;   // [MT][STA]  z tile    33.8 KB

    int t = threadIdx.x, lane = t & 31, w = t >> 5;
    int gid = lane >> 2, tig = lane & 3;
    int wm = w & 1, wn = w >> 1;
    int hb = blockIdx.x, l = blockIdx.y;
    int h0 = hb * HT;

    uint32_t su_b  = (uint32_t)__cvta_generic_to_shared(su);
    uint32_t sp_b  = (uint32_t)__cvta_generic_to_shared(sp);
    uint32_t sze_b = (uint32_t)__cvta_generic_to_shared(sze);

    int off = g_offsets[l];
    int cnt = g_offsets[l + 1] - off;
    if (cnt == 0) return;

    // stage u tile (once): su[h][r]
    #pragma unroll
    for (int i = 0; i < (HT * 16) / TPB; i++) {             // 8 iters
        int idx = t + i * TPB;
        int row = idx >> 4, c4 = idx & 15;
        cpa16(su_b + (row * STU + c4 * 4) * 4,
              u + ((size_t)l * HH + h0 + row) * RNK + c4 * 4, 16);
    }

    for (int m0 = 0; m0 < cnt; m0 += MT) {
        int nc = min(MT, cnt - m0);
        __syncthreads();   // previous-iteration smem fully consumed
        // stage proj tile: 64 samples x 64 r
        #pragma unroll
        for (int i = 0; i < (MT * 16) / TPB; i++) {         // 4 iters
            int idx = t + i * TPB;
            int row = idx >> 4, c4 = idx & 15;
            const float* src = g_proj;
            uint32_t szb = 0;
            if (row < nc) {
                src = g_proj + (size_t)(off + m0 + row) * RNK + c4 * 4;
                szb = 16;
            }
            cpa16(sp_b + (row * STU + c4 * 4) * 4, src, szb);
        }
        // stage z epilogue tile: 64 samples x 128 h
        #pragma unroll
        for (int i = 0; i < (MT * 32) / TPB; i++) {         // 8 iters
            int idx = t + i * TPB;
            int row = idx >> 5, c4 = idx & 31;
            const float* src = z;
            uint32_t szb = 0;
            if (row < nc) {
                int gs = g_sorted[off + m0 + row];
                src = z + (size_t)gs * HH + h0 + c4 * 4;
                szb = 16;
            }
            cpa16(sze_b + (row * STA + c4 * 4) * 4, src, szb);
        }
        cpa_commit_wait();   // single exposed wait (covers u on first iter)
        __syncthreads();

        float acc[2][4][4];
        #pragma unroll
        for (int mt = 0; mt < 2; mt++)
            #pragma unroll
            for (int j = 0; j < 4; j++)
                #pragma unroll
                for (int q = 0; q < 4; q++) acc[mt][j][q] = 0.0f;

        #pragma unroll
        for (int ks = 0; ks < 8; ks++) {
            int kb = ks * 8 + tig;
            uint32_t b0[4], b1[4];
            #pragma unroll
            for (int j = 0; j < 4; j++) {
                int n = wn * 32 + j * 8 + gid;
                b0[j] = su[n * STU + kb];
                b1[j] = su[n * STU + kb + 4];
            }
            #pragma unroll
            for (int mt = 0; mt < 2; mt++) {
                const uint32_t* spr = sp + (wm * 32 + mt * 16 + gid) * STU;
                uint32_t a0 = spr[kb];
                uint32_t a1 = spr[8 * STU + kb];
                uint32_t a2 = spr[kb + 4];
                uint32_t a3 = spr[8 * STU + kb + 4];
                #pragma unroll
                for (int j = 0; j < 4; j++)
                    MMA_TF32(acc[mt][j][0], acc[mt][j][1], acc[mt][j][2], acc[mt][j][3],
                             a0, a1, a2, a3, b0[j], b1[j]);
            }
        }

        // epilogue: out = z(smem) + delta, 8B stores (one 32B sector / 4 lanes)
        const float* szef = (const float*)sze;
        #pragma unroll
        for (int mt = 0; mt < 2; mt++) {
            #pragma unroll
            for (int half = 0; half < 2; half++) {
                int rr = wm * 32 + mt * 16 + gid + half * 8;
                if (rr < nc) {
                    int gs = g_sorted[off + m0 + rr];
                    float* orow = out + (size_t)gs * HH + h0;
                    const float* zrow = szef + rr * STA;
                    #pragma unroll
                    for (int j = 0; j < 4; j++) {
                        int col = wn * 32 + j * 8 + 2 * tig;
                        float2 zz = *(const float2*)&zrow[col];
                        *(float2*)&orow[col] = make_float2(zz.x + acc[mt][j][half * 2 + 0],
                                                           zz.y + acc[mt][j][half * 2 + 1]);
                    }
                }
            }
        }
    }
}

// ---------------------------------------------------------------------------
extern "C" void kernel_launch(void* const* d_in, const int* in_sizes, int n_in,
                              void* d_out, int out_size) {
    const float* z   = (const float*)d_in[0];
    const int*   ids = (const int*)  d_in[1];
    const float* u   = (const float*)d_in[2];
    const float* v   = (const float*)d_in[3];
    float*       out = (float*)d_out;

    const int proj_smem = (MT * STA + KST * STB) * 4;            // 70.7 KB
    const int out_smem  = (HT * STU + MT * STU + MT * STA) * 4;  // 86.0 KB
    cudaFuncSetAttribute(proj_kernel, cudaFuncAttributeMaxDynamicSharedMemorySize, proj_smem);
    cudaFuncSetAttribute(out_kernel,  cudaFuncAttributeMaxDynamicSharedMemorySize, out_smem);

    setup_kernel<<<1, 256>>>(ids);
    proj_kernel<<<dim3(NKG, LL), TPB, proj_smem>>>(z, v);
    reduce_kernel<<<(BB * RNK / 4 + 255) / 256, 256>>>();
    out_kernel<<<dim3(HH / HT, LL), TPB, out_smem>>>(z, u, out);
}

// round 8
// speedup vs baseline: 1.2513x; 1.0159x over previous
#include <cuda_runtime.h>
#include <cstdint>

// Problem constants
#define BB   2048
#define HH   2048
#define RNK  64
#define LL   32

#define NKG  8           // split-K groups for GEMM1 (k per block = 256)
#define KCH  (HH / NKG)  // 256
#define KST  64          // K staged per pipeline stage
#define MT   64          // M tile (samples)
#define HT   128         // h tile for GEMM2
#define TPB  256         // 8 warps
#define STZ  68          // stride sample-major z tile  (68 mod 32 == 4)
#define STB  72          // stride k-major v tile       (72 mod 32 == 8)
#define STU  68          // stride n-major u/proj tiles (68 mod 32 == 4)

#define ZW   (MT * STZ)        // words per z stage buffer
#define VW   (KST * STB)       // words per v stage buffer
#define BUFW (ZW + VW)

// Scratch (device globals — no allocations allowed)
__device__ int    g_offsets[LL + 1];
__device__ int    g_sorted[BB];
__device__ float  g_partial[(size_t)NKG * BB * RNK];   // 4 MB, indexed by sorted pos
__device__ float  g_proj[(size_t)BB * RNK];            // indexed by sorted pos

#define MMA_TF32(c0,c1,c2,c3,a0,a1,a2,a3,b0,b1)                         \
    asm("mma.sync.aligned.m16n8k8.row.col.f32.tf32.tf32.f32 "           \
        "{%0,%1,%2,%3}, {%4,%5,%6,%7}, {%8,%9}, {%0,%1,%2,%3};"         \
        : "+f"(c0), "+f"(c1), "+f"(c2), "+f"(c3)                        \
        : "r"(a0), "r"(a1), "r"(a2), "r"(a3), "r"(b0), "r"(b1))

__device__ __forceinline__ void cpa16(uint32_t dst, const void* src, uint32_t sz) {
    asm volatile("cp.async.cg.shared.global [%0], [%1], 16, %2;"
                 :: "r"(dst), "l"(src), "r"(sz));
}
__device__ __forceinline__ void cpa_commit() {
    asm volatile("cp.async.commit_group;");
}
__device__ __forceinline__ void cpa_wait0() {
    asm volatile("cp.async.wait_group 0;");
}
__device__ __forceinline__ void cpa_wait1() {
    asm volatile("cp.async.wait_group 1;");
}

// ---------------------------------------------------------------------------
// Kernel 1: stable counting sort of samples by layer id (deterministic).
// ---------------------------------------------------------------------------
__global__ void setup_kernel(const int* __restrict__ ids) {
    __shared__ int A[LL * 256];
    __shared__ int S[256];
    int t = threadIdx.x;

    #pragma unroll
    for (int l = 0; l < LL; l++) A[l * 256 + t] = 0;
    int seg = t * (BB / 256);
    #pragma unroll
    for (int i = 0; i < BB / 256; i++) {
        int lid = ids[seg + i];
        A[lid * 256 + t]++;
    }
    __syncthreads();

    int base = t * 32;
    int sum = 0;
    #pragma unroll
    for (int j = 0; j < 32; j++) { int x = A[base + j]; A[base + j] = sum; sum += x; }
    S[t] = sum;
    int mysum = sum;
    __syncthreads();
    for (int d = 1; d < 256; d <<= 1) {
        int add = (t >= d) ? S[t - d] : 0;
        __syncthreads();
        S[t] += add;
        __syncthreads();
    }
    int excl = S[t] - mysum;
    #pragma unroll
    for (int j = 0; j < 32; j++) A[base + j] += excl;
    __syncthreads();

    if (t < LL) g_offsets[t] = A[t * 256];
    if (t == 0) g_offsets[LL] = BB;

    #pragma unroll
    for (int i = 0; i < BB / 256; i++) {
        int s = seg + i;
        int lid = ids[s];
        int p = A[lid * 256 + t];
        A[lid * 256 + t] = p + 1;
        g_sorted[p] = s;
    }
}

// ---------------------------------------------------------------------------
// Kernel 2: GEMM1 split-K, tf32 mma, 2-stage cp.async pipeline.
// block = (kg in [0,8), layer); 8 warps; warp = m32 (wm) x n16 (wn).
// Iteration space flattened: it = (m-chunk * 4 + kk), KST=64 per stage.
// partial[kg][p][r] = sum_{k in chunk} v[l][k][r] * z[sorted[p]][k]
// ---------------------------------------------------------------------------
__global__ __launch_bounds__(TPB, 3) void proj_kernel(const float* __restrict__ z,
                                                      const float* __restrict__ v) {
    extern __shared__ __align__(16) uint32_t smem1[];   // 2 x (z[MT][STZ], v[KST][STB])

    int t = threadIdx.x, lane = t & 31, w = t >> 5;
    int gid = lane >> 2, tig = lane & 3;
    int wm = w & 1, wn = w >> 1;
    int kg = blockIdx.x, l = blockIdx.y;

    uint32_t sb = (uint32_t)__cvta_generic_to_shared(smem1);

    int off = g_offsets[l];
    int cnt = g_offsets[l + 1] - off;
    int nm = (cnt + MT - 1) / MT;
    int total = nm * 4;
    if (total == 0) return;

    // stage(it): load z[m-chunk][k-subchunk] and v[k-subchunk] into buffer it&1
    auto stage = [&](int it) {
        int m0 = (it >> 2) * MT;
        int nc = min(MT, cnt - m0);
        int k0 = kg * KCH + (it & 3) * KST;
        uint32_t zb = sb + (uint32_t)(it & 1) * BUFW * 4;
        uint32_t vb = zb + ZW * 4;
        #pragma unroll
        for (int i = 0; i < (MT * 16) / TPB; i++) {     // 4 iters: 64 rows x 16 float4
            int idx = t + i * TPB;
            int row = idx >> 4, c4 = idx & 15;
            const float* src = z;
            uint32_t szb = 0;
            if (row < nc) {
                int gs = g_sorted[off + m0 + row];
                src = z + (size_t)gs * HH + k0 + c4 * 4;
                szb = 16;
            }
            cpa16(zb + (row * STZ + c4 * 4) * 4, src, szb);
        }
        #pragma unroll
        for (int i = 0; i < (KST * 16) / TPB; i++) {    // 4 iters: 64 k-rows x 16 float4
            int idx = t + i * TPB;
            int row = idx >> 4, c4 = idx & 15;
            cpa16(vb + (row * STB + c4 * 4) * 4,
                  v + ((size_t)l * HH + k0 + row) * RNK + c4 * 4, 16);
        }
        cpa_commit();
    };

    stage(0);
    if (total > 1) stage(1);

    float acc[2][2][4];
    for (int it = 0; it < total; it++) {
        int kk = it & 3;
        if (kk == 0) {
            #pragma unroll
            for (int mt = 0; mt < 2; mt++)
                #pragma unroll
                for (int j = 0; j < 2; j++)
                    #pragma unroll
                    for (int q = 0; q < 4; q++) acc[mt][j][q] = 0.0f;
        }
        if (it + 2 <= total) cpa_wait1(); else cpa_wait0();
        __syncthreads();

        const uint32_t* zt = smem1 + (it & 1) * BUFW;
        const uint32_t* vt = zt + ZW;

        #pragma unroll
        for (int ks = 0; ks < KST / 8; ks++) {          // 8 iters
            int kb = ks * 8 + tig;
            uint32_t b0[2], b1[2];
            #pragma unroll
            for (int j = 0; j < 2; j++) {
                int n = wn * 16 + j * 8 + gid;
                b0[j] = vt[kb * STB + n];
                b1[j] = vt[(kb + 4) * STB + n];
            }
            #pragma unroll
            for (int mt = 0; mt < 2; mt++) {
                const uint32_t* zr = zt + (wm * 32 + mt * 16 + gid) * STZ;
                uint32_t a0 = zr[kb];
                uint32_t a1 = zr[8 * STZ + kb];
                uint32_t a2 = zr[kb + 4];
                uint32_t a3 = zr[8 * STZ + kb + 4];
                #pragma unroll
                for (int j = 0; j < 2; j++)
                    MMA_TF32(acc[mt][j][0], acc[mt][j][1], acc[mt][j][2], acc[mt][j][3],
                             a0, a1, a2, a3, b0[j], b1[j]);
            }
        }
        __syncthreads();
        if (it + 2 < total) stage(it + 2);

        if (kk == 3) {
            int m0 = (it >> 2) * MT;
            int nc = min(MT, cnt - m0);
            float* pb = g_partial + (size_t)kg * BB * RNK;
            #pragma unroll
            for (int mt = 0; mt < 2; mt++) {
                int rbase = wm * 32 + mt * 16 + gid;
                #pragma unroll
                for (int j = 0; j < 2; j++) {
                    int col = wn * 16 + j * 8 + 2 * tig;
                    if (rbase < nc)
                        *(float2*)&pb[(size_t)(off + m0 + rbase) * RNK + col] =
                            make_float2(acc[mt][j][0], acc[mt][j][1]);
                    if (rbase + 8 < nc)
                        *(float2*)&pb[(size_t)(off + m0 + rbase + 8) * RNK + col] =
                            make_float2(acc[mt][j][2], acc[mt][j][3]);
                }
            }
        }
    }
}

// ---------------------------------------------------------------------------
// Kernel 3: deterministic split-K reduction (8 groups).
// ---------------------------------------------------------------------------
__global__ void reduce_kernel() {
    int i = blockIdx.x * blockDim.x + threadIdx.x;
    const int n4 = BB * RNK / 4;
    if (i >= n4) return;
    const float4* p = (const float4*)g_partial;
    float4 s = p[i];
    #pragma unroll
    for (int kc = 1; kc < NKG; kc++) {
        float4 q = p[(size_t)kc * n4 + i];
        s.x += q.x; s.y += q.y; s.z += q.z; s.w += q.w;
    }
    ((float4*)g_proj)[i] = s;
}

// ---------------------------------------------------------------------------
// Kernel 4: GEMM2 + epilogue. u + proj staged via cp.async; epilogue z
// prefetched into REGISTERS before the MMA loop (hidden behind MMA).
// block = (h-tile 128, layer); 8 warps; warp = m32 (wm) x n32 (wn).
// ---------------------------------------------------------------------------
__global__ __launch_bounds__(TPB, 3) void out_kernel(const float* __restrict__ z,
                                                     const float* __restrict__ u,
                                                     float* __restrict__ out) {
    extern __shared__ __align__(16) uint32_t smem2[];
    uint32_t* su = smem2;                  // [HT][STU]  u tile    34.8 KB
    uint32_t* sp = smem2 + HT * STU;       // [MT][STU]  proj tile 17.4 KB

    int t = threadIdx.x, lane = t & 31, w = t >> 5;
    int gid = lane >> 2, tig = lane & 3;
    int wm = w & 1, wn = w >> 1;
    int hb = blockIdx.x, l = blockIdx.y;
    int h0 = hb * HT;

    uint32_t su_b = (uint32_t)__cvta_generic_to_shared(su);
    uint32_t sp_b = (uint32_t)__cvta_generic_to_shared(sp);

    int off = g_offsets[l];
    int cnt = g_offsets[l + 1] - off;
    if (cnt == 0) return;

    // stage u tile (once): su[h][r]
    #pragma unroll
    for (int i = 0; i < (HT * 16) / TPB; i++) {             // 8 iters
        int idx = t + i * TPB;
        int row = idx >> 4, c4 = idx & 15;
        cpa16(su_b + (row * STU + c4 * 4) * 4,
              u + ((size_t)l * HH + h0 + row) * RNK + c4 * 4, 16);
    }
    cpa_commit();

    for (int m0 = 0; m0 < cnt; m0 += MT) {
        int nc = min(MT, cnt - m0);
        __syncthreads();   // previous-iteration sp consumed
        #pragma unroll
        for (int i = 0; i < (MT * 16) / TPB; i++) {         // 4 iters
            int idx = t + i * TPB;
            int row = idx >> 4, c4 = idx & 15;
            const float* src = g_proj;
            uint32_t szb = 0;
            if (row < nc) {
                src = g_proj + (size_t)(off + m0 + row) * RNK + c4 * 4;
                szb = 16;
            }
            cpa16(sp_b + (row * STU + c4 * 4) * 4, src, szb);
        }
        cpa_commit();
        cpa_wait0();
        __syncthreads();

        // prefetch epilogue z into registers (overlaps with MMA below)
        int   gsr[2][2];
        float2 zpre[2][2][4];
        #pragma unroll
        for (int mt = 0; mt < 2; mt++)
            #pragma unroll
            for (int half = 0; half < 2; half++) {
                int rr = wm * 32 + mt * 16 + gid + half * 8;
                int rid = (rr < nc) ? rr : 0;
                int gs = g_sorted[off + m0 + rid];
                gsr[mt][half] = gs;
                const float* zrow = z + (size_t)gs * HH + h0;
                #pragma unroll
                for (int j = 0; j < 4; j++)
                    zpre[mt][half][j] = *(const float2*)&zrow[wn * 32 + j * 8 + 2 * tig];
            }

        float acc[2][4][4];
        #pragma unroll
        for (int mt = 0; mt < 2; mt++)
            #pragma unroll
            for (int j = 0; j < 4; j++)
                #pragma unroll
                for (int q = 0; q < 4; q++) acc[mt][j][q] = 0.0f;

        #pragma unroll
        for (int ks = 0; ks < 8; ks++) {
            int kb = ks * 8 + tig;
            uint32_t b0[4], b1[4];
            #pragma unroll
            for (int j = 0; j < 4; j++) {
                int n = wn * 32 + j * 8 + gid;
                b0[j] = su[n * STU + kb];
                b1[j] = su[n * STU + kb + 4];
            }
            #pragma unroll
            for (int mt = 0; mt < 2; mt++) {
                const uint32_t* spr = sp + (wm * 32 + mt * 16 + gid) * STU;
                uint32_t a0 = spr[kb];
                uint32_t a1 = spr[8 * STU + kb];
                uint32_t a2 = spr[kb + 4];
                uint32_t a3 = spr[8 * STU + kb + 4];
                #pragma unroll
                for (int j = 0; j < 4; j++)
                    MMA_TF32(acc[mt][j][0], acc[mt][j][1], acc[mt][j][2], acc[mt][j][3],
                             a0, a1, a2, a3, b0[j], b1[j]);
            }
        }

        // epilogue: out = z(regs) + delta
        #pragma unroll
        for (int mt = 0; mt < 2; mt++) {
            #pragma unroll
            for (int half = 0; half < 2; half++) {
                int rr = wm * 32 + mt * 16 + gid + half * 8;
                if (rr < nc) {
                    float* orow = out + (size_t)gsr[mt][half] * HH + h0;
                    #pragma unroll
                    for (int j = 0; j < 4; j++) {
                        int col = wn * 32 + j * 8 + 2 * tig;
                        float2 zz = zpre[mt][half][j];
                        *(float2*)&orow[col] = make_float2(zz.x + acc[mt][j][half * 2 + 0],
                                                           zz.y + acc[mt][j][half * 2 + 1]);
                    }
                }
            }
        }
    }
}

// ---------------------------------------------------------------------------
extern "C" void kernel_launch(void* const* d_in, const int* in_sizes, int n_in,
                              void* d_out, int out_size) {
    const float* z   = (const float*)d_in[0];
    const int*   ids = (const int*)  d_in[1];
    const float* u   = (const float*)d_in[2];
    const float* v   = (const float*)d_in[3];
    float*       out = (float*)d_out;

    const int proj_smem = 2 * BUFW * 4;                  // 71.7 KB
    const int out_smem  = (HT * STU + MT * STU) * 4;     // 52.2 KB
    cudaFuncSetAttribute(proj_kernel, cudaFuncAttributeMaxDynamicSharedMemorySize, proj_smem);
    cudaFuncSetAttribute(out_kernel,  cudaFuncAttributeMaxDynamicSharedMemorySize, out_smem);

    setup_kernel<<<1, 256>>>(ids);
    proj_kernel<<<dim3(NKG, LL), TPB, proj_smem>>>(z, v);
    reduce_kernel<<<(BB * RNK / 4 + 255) / 256, 256>>>();
    out_kernel<<<dim3(HH / HT, LL), TPB, out_smem>>>(z, u, out);
}

// round 9
// speedup vs baseline: 1.3058x; 1.0435x over previous
#include <cuda_runtime.h>
#include <cstdint>

// Problem constants
#define BB   2048
#define HH   2048
#define RNK  64
#define LL   32

#define NKG  16          // split-K groups for GEMM1 (k per block = 128)
#define KCH  (HH / NKG)  // 128
#define KST  64          // K staged per pipeline stage (2 stages per m-chunk)
#define MT   64          // M tile (samples)
#define HT   64          // h tile for GEMM2
#define TPB  256         // proj: 8 warps
#define OTPB 128         // out: 4 warps
#define STZ  68          // stride sample-major z tile  (68 mod 32 == 4)
#define STB  72          // stride k-major v tile       (72 mod 32 == 8)
#define STU  68          // stride n-major u/proj tiles (68 mod 32 == 4)

#define ZW   (MT * STZ)        // words per z stage buffer
#define VW   (KST * STB)       // words per v stage buffer
#define BUFW (ZW + VW)

// Scratch (device globals — no allocations allowed)
__device__ int    g_offsets[LL + 1];
__device__ int    g_sorted[BB];
__device__ float  g_partial[(size_t)NKG * BB * RNK];   // 8 MB, indexed by sorted pos
__device__ float  g_proj[(size_t)BB * RNK];            // indexed by sorted pos

#define MMA_TF32(c0,c1,c2,c3,a0,a1,a2,a3,b0,b1)                         \
    asm("mma.sync.aligned.m16n8k8.row.col.f32.tf32.tf32.f32 "           \
        "{%0,%1,%2,%3}, {%4,%5,%6,%7}, {%8,%9}, {%0,%1,%2,%3};"         \
        : "+f"(c0), "+f"(c1), "+f"(c2), "+f"(c3)                        \
        : "r"(a0), "r"(a1), "r"(a2), "r"(a3), "r"(b0), "r"(b1))

__device__ __forceinline__ void cpa16(uint32_t dst, const void* src, uint32_t sz) {
    asm volatile("cp.async.cg.shared.global [%0], [%1], 16, %2;"
                 :: "r"(dst), "l"(src), "r"(sz));
}
__device__ __forceinline__ void cpa_commit() { asm volatile("cp.async.commit_group;"); }
__device__ __forceinline__ void cpa_wait0()  { asm volatile("cp.async.wait_group 0;"); }
__device__ __forceinline__ void cpa_wait1()  { asm volatile("cp.async.wait_group 1;"); }

// ---------------------------------------------------------------------------
// Kernel 1: stable counting sort of samples by layer id (deterministic).
// ---------------------------------------------------------------------------
__global__ void setup_kernel(const int* __restrict__ ids) {
    __shared__ int A[LL * 256];
    __shared__ int S[256];
    int t = threadIdx.x;

    #pragma unroll
    for (int l = 0; l < LL; l++) A[l * 256 + t] = 0;
    int seg = t * (BB / 256);
    #pragma unroll
    for (int i = 0; i < BB / 256; i++) {
        int lid = ids[seg + i];
        A[lid * 256 + t]++;
    }
    __syncthreads();

    int base = t * 32;
    int sum = 0;
    #pragma unroll
    for (int j = 0; j < 32; j++) { int x = A[base + j]; A[base + j] = sum; sum += x; }
    S[t] = sum;
    int mysum = sum;
    __syncthreads();
    for (int d = 1; d < 256; d <<= 1) {
        int add = (t >= d) ? S[t - d] : 0;
        __syncthreads();
        S[t] += add;
        __syncthreads();
    }
    int excl = S[t] - mysum;
    #pragma unroll
    for (int j = 0; j < 32; j++) A[base + j] += excl;
    __syncthreads();

    if (t < LL) g_offsets[t] = A[t * 256];
    if (t == 0) g_offsets[LL] = BB;

    #pragma unroll
    for (int i = 0; i < BB / 256; i++) {
        int s = seg + i;
        int lid = ids[s];
        int p = A[lid * 256 + t];
        A[lid * 256 + t] = p + 1;
        g_sorted[p] = s;
    }
}

// ---------------------------------------------------------------------------
// Kernel 2: GEMM1 split-K, tf32 mma, 2-stage cp.async pipeline.
// block = (kg in [0,16), layer); 8 warps; warp = m32 (wm) x n16 (wn).
// it = (m-chunk * 2 + kk), KST=64 per stage, KCH=128 per block.
// partial[kg][p][r] = sum_{k in chunk} v[l][k][r] * z[sorted[p]][k]
// ---------------------------------------------------------------------------
__global__ __launch_bounds__(TPB, 3) void proj_kernel(const float* __restrict__ z,
                                                      const float* __restrict__ v) {
    extern __shared__ __align__(16) uint32_t smem1[];   // 2 x (z[MT][STZ], v[KST][STB])

    int t = threadIdx.x, lane = t & 31, w = t >> 5;
    int gid = lane >> 2, tig = lane & 3;
    int wm = w & 1, wn = w >> 1;
    int kg = blockIdx.x, l = blockIdx.y;

    uint32_t sb = (uint32_t)__cvta_generic_to_shared(smem1);

    int off = g_offsets[l];
    int cnt = g_offsets[l + 1] - off;
    int nm = (cnt + MT - 1) / MT;
    int total = nm * 2;
    if (total == 0) return;

    auto stage = [&](int it) {
        int m0 = (it >> 1) * MT;
        int nc = min(MT, cnt - m0);
        int k0 = kg * KCH + (it & 1) * KST;
        uint32_t zb = sb + (uint32_t)(it & 1) * BUFW * 4;
        uint32_t vb = zb + ZW * 4;
        #pragma unroll
        for (int i = 0; i < (MT * 16) / TPB; i++) {     // 4 iters
            int idx = t + i * TPB;
            int row = idx >> 4, c4 = idx & 15;
            const float* src = z;
            uint32_t szb = 0;
            if (row < nc) {
                int gs = g_sorted[off + m0 + row];
                src = z + (size_t)gs * HH + k0 + c4 * 4;
                szb = 16;
            }
            cpa16(zb + (row * STZ + c4 * 4) * 4, src, szb);
        }
        #pragma unroll
        for (int i = 0; i < (KST * 16) / TPB; i++) {    // 4 iters
            int idx = t + i * TPB;
            int row = idx >> 4, c4 = idx & 15;
            cpa16(vb + (row * STB + c4 * 4) * 4,
                  v + ((size_t)l * HH + k0 + row) * RNK + c4 * 4, 16);
        }
        cpa_commit();
    };

    stage(0);
    if (total > 1) stage(1);

    float acc[2][2][4];
    for (int it = 0; it < total; it++) {
        int kk = it & 1;
        if (kk == 0) {
            #pragma unroll
            for (int mt = 0; mt < 2; mt++)
                #pragma unroll
                for (int j = 0; j < 2; j++)
                    #pragma unroll
                    for (int q = 0; q < 4; q++) acc[mt][j][q] = 0.0f;
        }
        if (it + 2 <= total) cpa_wait1(); else cpa_wait0();
        __syncthreads();

        const uint32_t* zt = smem1 + (it & 1) * BUFW;
        const uint32_t* vt = zt + ZW;

        #pragma unroll
        for (int ks = 0; ks < KST / 8; ks++) {          // 8 iters
            int kb = ks * 8 + tig;
            uint32_t b0[2], b1[2];
            #pragma unroll
            for (int j = 0; j < 2; j++) {
                int n = wn * 16 + j * 8 + gid;
                b0[j] = vt[kb * STB + n];
                b1[j] = vt[(kb + 4) * STB + n];
            }
            #pragma unroll
            for (int mt = 0; mt < 2; mt++) {
                const uint32_t* zr = zt + (wm * 32 + mt * 16 + gid) * STZ;
                uint32_t a0 = zr[kb];
                uint32_t a1 = zr[8 * STZ + kb];
                uint32_t a2 = zr[kb + 4];
                uint32_t a3 = zr[8 * STZ + kb + 4];
                #pragma unroll
                for (int j = 0; j < 2; j++)
                    MMA_TF32(acc[mt][j][0], acc[mt][j][1], acc[mt][j][2], acc[mt][j][3],
                             a0, a1, a2, a3, b0[j], b1[j]);
            }
        }
        __syncthreads();
        if (it + 2 < total) stage(it + 2);

        if (kk == 1) {
            int m0 = (it >> 1) * MT;
            int nc = min(MT, cnt - m0);
            float* pb = g_partial + (size_t)kg * BB * RNK;
            #pragma unroll
            for (int mt = 0; mt < 2; mt++) {
                int rbase = wm * 32 + mt * 16 + gid;
                #pragma unroll
                for (int j = 0; j < 2; j++) {
                    int col = wn * 16 + j * 8 + 2 * tig;
                    if (rbase < nc)
                        *(float2*)&pb[(size_t)(off + m0 + rbase) * RNK + col] =
                            make_float2(acc[mt][j][0], acc[mt][j][1]);
                    if (rbase + 8 < nc)
                        *(float2*)&pb[(size_t)(off + m0 + rbase + 8) * RNK + col] =
                            make_float2(acc[mt][j][2], acc[mt][j][3]);
                }
            }
        }
    }
}

// ---------------------------------------------------------------------------
// Kernel 3: deterministic split-K reduction (16 groups).
// ---------------------------------------------------------------------------
__global__ void reduce_kernel() {
    int i = blockIdx.x * blockDim.x + threadIdx.x;
    const int n4 = BB * RNK / 4;
    if (i >= n4) return;
    const float4* p = (const float4*)g_partial;
    float4 s = p[i];
    #pragma unroll
    for (int kc = 1; kc < NKG; kc++) {
        float4 q = p[(size_t)kc * n4 + i];
        s.x += q.x; s.y += q.y; s.z += q.z; s.w += q.w;
    }
    ((float4*)g_proj)[i] = s;
}

// ---------------------------------------------------------------------------
// Kernel 4: GEMM2 + epilogue. 64x64 tiles, 4 warps (warp = m32 x n32),
// 1024 blocks -> high block-level parallelism. Epilogue z prefetched to regs.
// ---------------------------------------------------------------------------
__global__ __launch_bounds__(OTPB, 6) void out_kernel(const float* __restrict__ z,
                                                      const float* __restrict__ u,
                                                      float* __restrict__ out) {
    extern __shared__ __align__(16) uint32_t smem2[];
    uint32_t* su = smem2;                  // [HT][STU]  u tile    17.4 KB
    uint32_t* sp = smem2 + HT * STU;       // [MT][STU]  proj tile 17.4 KB

    int t = threadIdx.x, lane = t & 31, w = t >> 5;
    int gid = lane >> 2, tig = lane & 3;
    int wm = w & 1, wn = w >> 1;           // 4 warps: m32 x n32
    int hb = blockIdx.x, l = blockIdx.y;
    int h0 = hb * HT;

    uint32_t su_b = (uint32_t)__cvta_generic_to_shared(su);
    uint32_t sp_b = (uint32_t)__cvta_generic_to_shared(sp);

    int off = g_offsets[l];
    int cnt = g_offsets[l + 1] - off;
    if (cnt == 0) return;

    // stage u tile (once): su[h][r], 64 rows x 16 float4
    #pragma unroll
    for (int i = 0; i < (HT * 16) / OTPB; i++) {            // 8 iters
        int idx = t + i * OTPB;
        int row = idx >> 4, c4 = idx & 15;
        cpa16(su_b + (row * STU + c4 * 4) * 4,
              u + ((size_t)l * HH + h0 + row) * RNK + c4 * 4, 16);
    }
    cpa_commit();

    for (int m0 = 0; m0 < cnt; m0 += MT) {
        int nc = min(MT, cnt - m0);
        __syncthreads();   // previous-iteration sp consumed
        #pragma unroll
        for (int i = 0; i < (MT * 16) / OTPB; i++) {        // 8 iters
            int idx = t + i * OTPB;
            int row = idx >> 4, c4 = idx & 15;
            const float* src = g_proj;
            uint32_t szb = 0;
            if (row < nc) {
                src = g_proj + (size_t)(off + m0 + row) * RNK + c4 * 4;
                szb = 16;
            }
            cpa16(sp_b + (row * STU + c4 * 4) * 4, src, szb);
        }
        cpa_commit();
        cpa_wait0();
        __syncthreads();

        // prefetch epilogue z into registers (overlaps with MMA below)
        int    gsr[2][2];
        float2 zpre[2][2][4];
        #pragma unroll
        for (int mt = 0; mt < 2; mt++)
            #pragma unroll
            for (int half = 0; half < 2; half++) {
                int rr = wm * 32 + mt * 16 + gid + half * 8;
                int rid = (rr < nc) ? rr : 0;
                int gs = g_sorted[off + m0 + rid];
                gsr[mt][half] = gs;
                const float* zrow = z + (size_t)gs * HH + h0;
                #pragma unroll
                for (int j = 0; j < 4; j++)
                    zpre[mt][half][j] = *(const float2*)&zrow[wn * 32 + j * 8 + 2 * tig];
            }

        float acc[2][4][4];
        #pragma unroll
        for (int mt = 0; mt < 2; mt++)
            #pragma unroll
            for (int j = 0; j < 4; j++)
                #pragma unroll
                for (int q = 0; q < 4; q++) acc[mt][j][q] = 0.0f;

        #pragma unroll
        for (int ks = 0; ks < 8; ks++) {
            int kb = ks * 8 + tig;
            uint32_t b0[4], b1[4];
            #pragma unroll
            for (int j = 0; j < 4; j++) {
                int n = wn * 32 + j * 8 + gid;
                b0[j] = su[n * STU + kb];
                b1[j] = su[n * STU + kb + 4];
            }
            #pragma unroll
            for (int mt = 0; mt < 2; mt++) {
                const uint32_t* spr = sp + (wm * 32 + mt * 16 + gid) * STU;
                uint32_t a0 = spr[kb];
                uint32_t a1 = spr[8 * STU + kb];
                uint32_t a2 = spr[kb + 4];
                uint32_t a3 = spr[8 * STU + kb + 4];
                #pragma unroll
                for (int j = 0; j < 4; j++)
                    MMA_TF32(acc[mt][j][0], acc[mt][j][1], acc[mt][j][2], acc[mt][j][3],
                             a0, a1, a2, a3, b0[j], b1[j]);
            }
        }

        // epilogue: out = z(regs) + delta
        #pragma unroll
        for (int mt = 0; mt < 2; mt++) {
            #pragma unroll
            for (int half = 0; half < 2; half++) {
                int rr = wm * 32 + mt * 16 + gid + half * 8;
                if (rr < nc) {
                    float* orow = out + (size_t)gsr[mt][half] * HH + h0;
                    #pragma unroll
                    for (int j = 0; j < 4; j++) {
                        int col = wn * 32 + j * 8 + 2 * tig;
                        float2 zz = zpre[mt][half][j];
                        *(float2*)&orow[col] = make_float2(zz.x + acc[mt][j][half * 2 + 0],
                                                           zz.y + acc[mt][j][half * 2 + 1]);
                    }
                }
            }
        }
    }
}

// ---------------------------------------------------------------------------
extern "C" void kernel_launch(void* const* d_in, const int* in_sizes, int n_in,
                              void* d_out, int out_size) {
    const float* z   = (const float*)d_in[0];
    const int*   ids = (const int*)  d_in[1];
    const float* u   = (const float*)d_in[2];
    const float* v   = (const float*)d_in[3];
    float*       out = (float*)d_out;

    const int proj_smem = 2 * BUFW * 4;                  // 71.7 KB
    const int out_smem  = (HT * STU + MT * STU) * 4;     // 34.8 KB
    cudaFuncSetAttribute(proj_kernel, cudaFuncAttributeMaxDynamicSharedMemorySize, proj_smem);
    cudaFuncSetAttribute(out_kernel,  cudaFuncAttributeMaxDynamicSharedMemorySize, out_smem);

    setup_kernel<<<1, 256>>>(ids);
    proj_kernel<<<dim3(NKG, LL), TPB, proj_smem>>>(z, v);
    reduce_kernel<<<(BB * RNK / 4 + 255) / 256, 256>>>();
    out_kernel<<<dim3(HH / HT, LL), OTPB, out_smem>>>(z, u, out);
}